// round 4
// baseline (speedup 1.0000x reference)
#include <cuda_runtime.h>
#include <cstdint>

#define DIN  1024
#define DH   512
#define NB   8192
#define DOUT 512

#define MT 32            // rows per tile in recurrent kernel
#define NT 512           // threads per CTA (16 warps -> 4 per SMSP)
#define KC 8             // k-chunk staged in smem
#define NCHUNK (DH / KC) // 64
// smem: hh + xeb + h (each MT*DH f32) + W double buffer (2*KC*DH f32)
#define REC_SMEM_BYTES ((3 * MT * DH + 2 * KC * DH) * 4)  // 229376

typedef unsigned long long ull;

// ---------------- scratch (static device allocations: allowed) ----------------
__device__ float g_sigma;
__device__ __align__(16) float g_Wt[DH * DH];     // Wt[k][n] = W[n][k]/sigma
__device__ __align__(16) float g_Wet[DIN * DH];   // Wet[d][j] = We[j][d]
__device__ __align__(16) float g_Wht[DH * DOUT];  // Wht[k][o] = Wh[o][k]
__device__ __align__(16) float g_xemb[NB * DH];
__device__ __align__(16) float g_h[NB * DH];

// ---------------- helpers ----------------
__device__ __forceinline__ ull pk2(float x, float y) {
    ull r;
    asm("mov.b64 %0, {%1,%2};" : "=l"(r) : "f"(x), "f"(y));
    return r;
}
__device__ __forceinline__ void upk2(ull a, float& x, float& y) {
    asm("mov.b64 {%0,%1}, %2;" : "=f"(x), "=f"(y) : "l"(a));
}
// packed fp32x2 FMA (Blackwell): 2x FFMA throughput
__device__ __forceinline__ ull fma2(ull a, ull b, ull c) {
    ull d;
    asm("fma.rn.f32x2 %0, %1, %2, %3;" : "=l"(d) : "l"(a), "l"(b), "l"(c));
    return d;
}
// accurate-enough tanh (~1e-6), immune to -use_fast_math lowering of tanhf
__device__ __forceinline__ float fast_tanh(float x) {
    float a = fabsf(x);
    float e = exp2f(-2.8853900817779268f * a);  // exp(-2a)
    float r = __fdividef(1.0f - e, 1.0f + e);
    return copysignf(r, x);
}

// ---------------- kernel 1: sigma = power-iteration spectral norm ----------------
__global__ void k_sigma(const float* __restrict__ W, const float* __restrict__ u) {
    __shared__ float sv[DH];
    __shared__ float red[DH];
    int t = threadIdx.x;  // 512 threads

    float acc = 0.f;
    for (int i = 0; i < DH; i++) acc += W[(size_t)i * DH + t] * u[i];
    sv[t] = acc;
    red[t] = acc * acc;
    __syncthreads();
    for (int s = 256; s > 0; s >>= 1) {
        if (t < s) red[t] += red[t + s];
        __syncthreads();
    }
    float inv1 = 1.f / (sqrtf(red[0]) + 1e-12f);
    __syncthreads();
    sv[t] *= inv1;  // v
    __syncthreads();
    float sacc = 0.f;
    const float* wr = W + (size_t)t * DH;
    for (int j = 0; j < DH; j++) sacc += wr[j] * sv[j];
    red[t] = sacc * sacc;
    __syncthreads();
    for (int s = 256; s > 0; s >>= 1) {
        if (t < s) red[t] += red[t + s];
        __syncthreads();
    }
    if (t == 0) {
        float ss = red[0];
        g_sigma = ss / (sqrtf(ss) + 1e-12f);
    }
}

// ---------------- kernel 2: scaled/transposed weight prep ----------------
__global__ void k_prep(const float* __restrict__ W, const float* __restrict__ We,
                       const float* __restrict__ Wh) {
    float inv = 1.0f / g_sigma;
    int stride = gridDim.x * blockDim.x;
    int t0 = blockIdx.x * blockDim.x + threadIdx.x;
    for (int idx = t0; idx < DH * DH; idx += stride) {
        int k = idx >> 9, n = idx & 511;
        g_Wt[idx] = W[(size_t)n * DH + k] * inv;
    }
    for (int idx = t0; idx < DIN * DH; idx += stride) {
        int d = idx >> 9, j = idx & 511;
        g_Wet[idx] = We[(size_t)j * DIN + d];
    }
    for (int idx = t0; idx < DH * DOUT; idx += stride) {
        int k = idx / DOUT, o = idx - k * DOUT;
        g_Wht[idx] = Wh[(size_t)o * DH + k];
    }
}

// ---------------- generic tiled GEMM: C[M,N] = A[M,K] @ Bt[K,N] + bias ----------------
__global__ __launch_bounds__(256) void k_gemm(const float* __restrict__ A,
                                              const float* __restrict__ Bt,
                                              const float* __restrict__ bias,
                                              float* __restrict__ C, int M, int N, int K) {
    __shared__ float As[16][64];  // As[k][m]
    __shared__ float Bs[16][64];  // Bs[k][n]
    int tid = threadIdx.x;
    int bx = blockIdx.x;  // N tile
    int by = blockIdx.y;  // M tile
    int tx = tid & 15, ty = tid >> 4;
    float accv[4][4];
#pragma unroll
    for (int i = 0; i < 4; i++)
#pragma unroll
        for (int j = 0; j < 4; j++) accv[i][j] = 0.f;

    for (int k0 = 0; k0 < K; k0 += 16) {
        {
            int r = tid >> 2;
            int c = (tid & 3) * 4;
            float4 av = *(const float4*)&A[(size_t)(by * 64 + r) * K + k0 + c];
            As[c + 0][r] = av.x;
            As[c + 1][r] = av.y;
            As[c + 2][r] = av.z;
            As[c + 3][r] = av.w;
        }
        {
            int kr = tid >> 4;
            int c = (tid & 15) * 4;
            float4 bv = *(const float4*)&Bt[(size_t)(k0 + kr) * N + bx * 64 + c];
            *(float4*)&Bs[kr][c] = bv;
        }
        __syncthreads();
#pragma unroll
        for (int k = 0; k < 16; k++) {
            float a[4], b[4];
#pragma unroll
            for (int i = 0; i < 4; i++) a[i] = As[k][ty * 4 + i];
#pragma unroll
            for (int j = 0; j < 4; j++) b[j] = Bs[k][tx * 4 + j];
#pragma unroll
            for (int i = 0; i < 4; i++)
#pragma unroll
                for (int j = 0; j < 4; j++) accv[i][j] += a[i] * b[j];
        }
        __syncthreads();
    }
#pragma unroll
    for (int i = 0; i < 4; i++) {
        int m = by * 64 + ty * 4 + i;
#pragma unroll
        for (int j = 0; j < 4; j++) {
            int n = bx * 64 + tx * 4 + j;
            C[(size_t)m * N + n] = accv[i][j] + bias[n];
        }
    }
}

// ---------------- kernel 3: fused recurrent core ----------------
__device__ __forceinline__ void cp_chunk(const float* __restrict__ Wt, float* sh_w, int c,
                                         int buf, int tid) {
    const float4* src = (const float4*)(Wt + (size_t)c * KC * DH);
    unsigned sbase = (unsigned)__cvta_generic_to_shared(sh_w + (size_t)buf * KC * DH);
#pragma unroll
    for (int r = 0; r < 2; r++) {
        int e = tid + r * NT;  // float4 index within 8x512 chunk (1024 total)
        asm volatile("cp.async.cg.shared.global [%0], [%1], 16;" ::"r"(sbase + e * 16),
                     "l"(src + e));
    }
}

__global__ __launch_bounds__(NT, 1) void k_recurrent(const float* __restrict__ bW,
                                                     const int* __restrict__ steps_p) {
    extern __shared__ float smem[];
    float* sh_hh = smem;                 // MT*DH : inner state (matmul A operand)
    float* sh_xeb = smem + MT * DH;      // MT*DH : x_emb + bW
    float* sh_h = smem + 2 * MT * DH;    // MT*DH : outer state h
    float* sh_w = smem + 3 * MT * DH;    // 2*KC*DH double buffer

    const int tid = threadIdx.x;
    const int tm = tid >> 7;   // 0..3 (row group)
    const int tn = tid & 127;  // 0..127
    const int ncol0 = 2 * tn;  // + 256*j, j in {0,1}
    const int row0 = blockIdx.x * MT;
    const float* __restrict__ Wt = g_Wt;

    // load x_emb + bW tile, zero h
    for (int idx = tid; idx < MT * DH; idx += NT) {
        int n = idx & (DH - 1);
        sh_xeb[idx] = g_xemb[(size_t)row0 * DH + idx] + bW[n];
        sh_h[idx] = 0.f;
    }

    const float* hrow[8];
#pragma unroll
    for (int i = 0; i < 8; i++) hrow[i] = sh_hh + (size_t)(tm + 4 * i) * DH;

    const int steps = steps_p[0];
    __syncthreads();

    for (int s = 0; s < steps; s++) {
        // ---- inner iter 0 (hh starts at 0 => matmul term is 0) ----
#pragma unroll
        for (int i = 0; i < 8; i++) {
            const size_t rb = (size_t)(tm + 4 * i) * DH;
#pragma unroll
            for (int j = 0; j < 2; j++) {
                int n0 = ncol0 + 256 * j;
                float2 xe = *(const float2*)(sh_xeb + rb + n0);
                float2 hv = *(const float2*)(sh_h + rb + n0);
                float2 o;
                o.x = 0.5f * fast_tanh(hv.x + xe.x);
                o.y = 0.5f * fast_tanh(hv.y + xe.y);
                *(float2*)(sh_hh + rb + n0) = o;
            }
        }
        __syncthreads();

        // ---- inner iters 1..4 : hh = 0.5 hh + 0.5 tanh(hh@Wt + h + xeb) ----
        for (int it = 1; it < 5; it++) {
            ull acc2[8][2];
#pragma unroll
            for (int i = 0; i < 8; i++) {
                acc2[i][0] = 0ull;
                acc2[i][1] = 0ull;
            }

            cp_chunk(Wt, sh_w, 0, 0, tid);
            asm volatile("cp.async.commit_group;" ::: "memory");

            for (int c = 0; c < NCHUNK; c++) {
                asm volatile("cp.async.wait_group 0;" ::: "memory");
                __syncthreads();
                if (c + 1 < NCHUNK) {
                    cp_chunk(Wt, sh_w, c + 1, (c + 1) & 1, tid);
                    asm volatile("cp.async.commit_group;" ::: "memory");
                }
                const float* wb = sh_w + (size_t)(c & 1) * KC * DH;
                const int k0 = c * KC;
#pragma unroll
                for (int kk = 0; kk < KC; kk += 2) {
                    float2 a2v[8];
#pragma unroll
                    for (int i = 0; i < 8; i++)
                        a2v[i] = *(const float2*)(hrow[i] + k0 + kk);
#pragma unroll
                    for (int q = 0; q < 2; q++) {
                        const float* wrow = wb + (kk + q) * DH;
                        ull w0 = *(const ull*)(wrow + ncol0);
                        ull w1 = *(const ull*)(wrow + ncol0 + 256);
#pragma unroll
                        for (int i = 0; i < 8; i++) {
                            float av = q ? a2v[i].y : a2v[i].x;
                            ull a2 = pk2(av, av);
                            acc2[i][0] = fma2(a2, w0, acc2[i][0]);
                            acc2[i][1] = fma2(a2, w1, acc2[i][1]);
                        }
                    }
                }
            }
            __syncthreads();  // all matmul reads of sh_hh complete

            // elementwise update of hh
#pragma unroll
            for (int i = 0; i < 8; i++) {
                const size_t rb = (size_t)(tm + 4 * i) * DH;
#pragma unroll
                for (int j = 0; j < 2; j++) {
                    int n0 = ncol0 + 256 * j;
                    float ax, ay;
                    upk2(acc2[i][j], ax, ay);
                    float2 xe = *(const float2*)(sh_xeb + rb + n0);
                    float2 hv = *(const float2*)(sh_h + rb + n0);
                    float2 old = *(const float2*)(sh_hh + rb + n0);
                    float2 nv;
                    nv.x = 0.5f * old.x + 0.5f * fast_tanh(ax + hv.x + xe.x);
                    nv.y = 0.5f * old.y + 0.5f * fast_tanh(ay + hv.y + xe.y);
                    *(float2*)(sh_hh + rb + n0) = nv;
                }
            }
            __syncthreads();  // hh visible for next matmul
        }

        // ---- outer update: h = 0.5 h + 0.5 hh ----
#pragma unroll
        for (int i = 0; i < 8; i++) {
            const size_t rb = (size_t)(tm + 4 * i) * DH;
#pragma unroll
            for (int j = 0; j < 2; j++) {
                int n0 = ncol0 + 256 * j;
                float2 hh = *(const float2*)(sh_hh + rb + n0);
                float2 hv = *(const float2*)(sh_h + rb + n0);
                hv.x = 0.5f * hv.x + 0.5f * hh.x;
                hv.y = 0.5f * hv.y + 0.5f * hh.y;
                *(float2*)(sh_h + rb + n0) = hv;
            }
        }
        __syncthreads();
    }

    // store final h
#pragma unroll
    for (int i = 0; i < 8; i++) {
        int m = row0 + tm + 4 * i;
        const size_t rb = (size_t)(tm + 4 * i) * DH;
#pragma unroll
        for (int j = 0; j < 2; j++) {
            int n0 = ncol0 + 256 * j;
            float2 hv = *(const float2*)(sh_h + rb + n0);
            *(float2*)&g_h[(size_t)m * DH + n0] = hv;
        }
    }
}

// ---------------- launch ----------------
extern "C" void kernel_launch(void* const* d_in, const int* in_sizes, int n_in, void* d_out,
                              int out_size) {
    const float* x = (const float*)d_in[0];
    const float* We = (const float*)d_in[1];
    const float* be = (const float*)d_in[2];
    const float* W = (const float*)d_in[3];
    const float* bW = (const float*)d_in[4];
    const float* u = (const float*)d_in[5];
    const float* Wh = (const float*)d_in[6];
    const float* bh = (const float*)d_in[7];
    const int* steps = (const int*)d_in[8];
    float* out = (float*)d_out;

    float *p_Wet, *p_Wht, *p_xemb, *p_h;
    cudaGetSymbolAddress((void**)&p_Wet, g_Wet);
    cudaGetSymbolAddress((void**)&p_Wht, g_Wht);
    cudaGetSymbolAddress((void**)&p_xemb, g_xemb);
    cudaGetSymbolAddress((void**)&p_h, g_h);

    cudaFuncSetAttribute(k_recurrent, cudaFuncAttributeMaxDynamicSharedMemorySize,
                         REC_SMEM_BYTES);

    k_sigma<<<1, 512>>>(W, u);
    k_prep<<<512, 256>>>(W, We, Wh);

    dim3 g1(DH / 64, NB / 64);
    k_gemm<<<g1, 256>>>(x, p_Wet, be, p_xemb, NB, DH, DIN);

    k_recurrent<<<NB / MT, NT, REC_SMEM_BYTES>>>(bW, steps);

    dim3 g2(DOUT / 64, NB / 64);
    k_gemm<<<g2, 256>>>(p_h, p_Wht, bh, out, NB, DOUT, DH);
}

// round 5
// speedup vs baseline: 1.0013x; 1.0013x over previous
#include <cuda_runtime.h>
#include <cstdint>

#define DIN  1024
#define DH   512
#define NB   8192
#define DOUT 512

#define MT 32            // rows per tile in recurrent kernel
#define NT 512           // threads per CTA (16 warps -> 4 per SMSP)
#define KC 8             // k-chunk staged in smem
#define NCHUNK (DH / KC) // 64
// smem: hh + xeb + h (each MT*DH f32) + W double buffer (2*KC*DH f32)
#define REC_SMEM_BYTES ((3 * MT * DH + 2 * KC * DH) * 4)  // 229376

typedef unsigned long long ull;

// ---------------- scratch (static device allocations: allowed) ----------------
__device__ float g_sigma;
__device__ __align__(16) float g_Wt[DH * DH];     // Wt[k][n] = W[n][k]/sigma
__device__ __align__(16) float g_Wet[DIN * DH];   // Wet[d][j] = We[j][d]
__device__ __align__(16) float g_Wht[DH * DOUT];  // Wht[k][o] = Wh[o][k]
__device__ __align__(16) float g_xemb[NB * DH];
__device__ __align__(16) float g_h[NB * DH];

// ---------------- helpers ----------------
__device__ __forceinline__ ull pk2(float x, float y) {
    ull r;
    asm("mov.b64 %0, {%1,%2};" : "=l"(r) : "f"(x), "f"(y));
    return r;
}
__device__ __forceinline__ void upk2(ull a, float& x, float& y) {
    asm("mov.b64 {%0,%1}, %2;" : "=f"(x), "=f"(y) : "l"(a));
}
// packed fp32x2 FMA (Blackwell): 2x FFMA throughput
__device__ __forceinline__ ull fma2(ull a, ull b, ull c) {
    ull d;
    asm("fma.rn.f32x2 %0, %1, %2, %3;" : "=l"(d) : "l"(a), "l"(b), "l"(c));
    return d;
}
// accurate-enough tanh (~1e-6), immune to -use_fast_math lowering of tanhf
__device__ __forceinline__ float fast_tanh(float x) {
    float a = fabsf(x);
    float e = exp2f(-2.8853900817779268f * a);  // exp(-2a)
    float r = __fdividef(1.0f - e, 1.0f + e);
    return copysignf(r, x);
}

// ---------------- kernel 1: sigma = power-iteration spectral norm ----------------
__global__ void k_sigma(const float* __restrict__ W, const float* __restrict__ u) {
    __shared__ float sv[DH];
    __shared__ float red[DH];
    int t = threadIdx.x;  // 512 threads

    float acc = 0.f;
    for (int i = 0; i < DH; i++) acc += W[(size_t)i * DH + t] * u[i];
    sv[t] = acc;
    red[t] = acc * acc;
    __syncthreads();
    for (int s = 256; s > 0; s >>= 1) {
        if (t < s) red[t] += red[t + s];
        __syncthreads();
    }
    float inv1 = 1.f / (sqrtf(red[0]) + 1e-12f);
    __syncthreads();
    sv[t] *= inv1;  // v
    __syncthreads();
    float sacc = 0.f;
    const float* wr = W + (size_t)t * DH;
    for (int j = 0; j < DH; j++) sacc += wr[j] * sv[j];
    red[t] = sacc * sacc;
    __syncthreads();
    for (int s = 256; s > 0; s >>= 1) {
        if (t < s) red[t] += red[t + s];
        __syncthreads();
    }
    if (t == 0) {
        float ss = red[0];
        g_sigma = ss / (sqrtf(ss) + 1e-12f);
    }
}

// ---------------- kernel 2: scaled/transposed weight prep ----------------
__global__ void k_prep(const float* __restrict__ W, const float* __restrict__ We,
                       const float* __restrict__ Wh) {
    float inv = 1.0f / g_sigma;
    int stride = gridDim.x * blockDim.x;
    int t0 = blockIdx.x * blockDim.x + threadIdx.x;
    for (int idx = t0; idx < DH * DH; idx += stride) {
        int k = idx >> 9, n = idx & 511;
        g_Wt[idx] = W[(size_t)n * DH + k] * inv;
    }
    for (int idx = t0; idx < DIN * DH; idx += stride) {
        int d = idx >> 9, j = idx & 511;
        g_Wet[idx] = We[(size_t)j * DIN + d];
    }
    for (int idx = t0; idx < DH * DOUT; idx += stride) {
        int k = idx / DOUT, o = idx - k * DOUT;
        g_Wht[idx] = Wh[(size_t)o * DH + k];
    }
}

// ---------------- generic tiled GEMM: C[M,N] = A[M,K] @ Bt[K,N] + bias ----------------
__global__ __launch_bounds__(256) void k_gemm(const float* __restrict__ A,
                                              const float* __restrict__ Bt,
                                              const float* __restrict__ bias,
                                              float* __restrict__ C, int M, int N, int K) {
    __shared__ float As[16][64];  // As[k][m]
    __shared__ float Bs[16][64];  // Bs[k][n]
    int tid = threadIdx.x;
    int bx = blockIdx.x;  // N tile
    int by = blockIdx.y;  // M tile
    int tx = tid & 15, ty = tid >> 4;
    float accv[4][4];
#pragma unroll
    for (int i = 0; i < 4; i++)
#pragma unroll
        for (int j = 0; j < 4; j++) accv[i][j] = 0.f;

    for (int k0 = 0; k0 < K; k0 += 16) {
        {
            int r = tid >> 2;
            int c = (tid & 3) * 4;
            float4 av = *(const float4*)&A[(size_t)(by * 64 + r) * K + k0 + c];
            As[c + 0][r] = av.x;
            As[c + 1][r] = av.y;
            As[c + 2][r] = av.z;
            As[c + 3][r] = av.w;
        }
        {
            int kr = tid >> 4;
            int c = (tid & 15) * 4;
            float4 bv = *(const float4*)&Bt[(size_t)(k0 + kr) * N + bx * 64 + c];
            *(float4*)&Bs[kr][c] = bv;
        }
        __syncthreads();
#pragma unroll
        for (int k = 0; k < 16; k++) {
            float a[4], b[4];
#pragma unroll
            for (int i = 0; i < 4; i++) a[i] = As[k][ty * 4 + i];
#pragma unroll
            for (int j = 0; j < 4; j++) b[j] = Bs[k][tx * 4 + j];
#pragma unroll
            for (int i = 0; i < 4; i++)
#pragma unroll
                for (int j = 0; j < 4; j++) accv[i][j] += a[i] * b[j];
        }
        __syncthreads();
    }
#pragma unroll
    for (int i = 0; i < 4; i++) {
        int m = by * 64 + ty * 4 + i;
#pragma unroll
        for (int j = 0; j < 4; j++) {
            int n = bx * 64 + tx * 4 + j;
            C[(size_t)m * N + n] = accv[i][j] + bias[n];
        }
    }
}

// ---------------- kernel 3: fused recurrent core ----------------
__device__ __forceinline__ void cp_chunk(const float* __restrict__ Wt, float* sh_w, int c,
                                         int buf, int tid) {
    const float4* src = (const float4*)(Wt + (size_t)c * KC * DH);
    unsigned sbase = (unsigned)__cvta_generic_to_shared(sh_w + (size_t)buf * KC * DH);
#pragma unroll
    for (int r = 0; r < 2; r++) {
        int e = tid + r * NT;  // float4 index within 8x512 chunk (1024 total)
        asm volatile("cp.async.cg.shared.global [%0], [%1], 16;" ::"r"(sbase + e * 16),
                     "l"(src + e));
    }
}

__global__ __launch_bounds__(NT, 1) void k_recurrent(const float* __restrict__ bW,
                                                     const int* __restrict__ steps_p) {
    extern __shared__ float smem[];
    float* sh_hh = smem;                 // MT*DH : inner state (matmul A operand)
    float* sh_xeb = smem + MT * DH;      // MT*DH : x_emb + bW
    float* sh_h = smem + 2 * MT * DH;    // MT*DH : outer state h
    float* sh_w = smem + 3 * MT * DH;    // 2*KC*DH double buffer

    const int tid = threadIdx.x;
    const int tm = tid >> 7;   // 0..3 (row group)
    const int tn = tid & 127;  // 0..127
    const int ncol0 = 2 * tn;  // + 256*j, j in {0,1}
    const int row0 = blockIdx.x * MT;
    const float* __restrict__ Wt = g_Wt;

    // load x_emb + bW tile, zero h
    for (int idx = tid; idx < MT * DH; idx += NT) {
        int n = idx & (DH - 1);
        sh_xeb[idx] = g_xemb[(size_t)row0 * DH + idx] + bW[n];
        sh_h[idx] = 0.f;
    }

    const float* hrow[8];
#pragma unroll
    for (int i = 0; i < 8; i++) hrow[i] = sh_hh + (size_t)(tm + 4 * i) * DH;

    const int steps = steps_p[0];
    __syncthreads();

    for (int s = 0; s < steps; s++) {
        // ---- inner iter 0 (hh starts at 0 => matmul term is 0) ----
#pragma unroll
        for (int i = 0; i < 8; i++) {
            const size_t rb = (size_t)(tm + 4 * i) * DH;
#pragma unroll
            for (int j = 0; j < 2; j++) {
                int n0 = ncol0 + 256 * j;
                float2 xe = *(const float2*)(sh_xeb + rb + n0);
                float2 hv = *(const float2*)(sh_h + rb + n0);
                float2 o;
                o.x = 0.5f * fast_tanh(hv.x + xe.x);
                o.y = 0.5f * fast_tanh(hv.y + xe.y);
                *(float2*)(sh_hh + rb + n0) = o;
            }
        }
        __syncthreads();

        // ---- inner iters 1..4 : hh = 0.5 hh + 0.5 tanh(hh@Wt + h + xeb) ----
        for (int it = 1; it < 5; it++) {
            ull acc2[8][2];
#pragma unroll
            for (int i = 0; i < 8; i++) {
                acc2[i][0] = 0ull;
                acc2[i][1] = 0ull;
            }

            cp_chunk(Wt, sh_w, 0, 0, tid);
            asm volatile("cp.async.commit_group;" ::: "memory");

            for (int c = 0; c < NCHUNK; c++) {
                asm volatile("cp.async.wait_group 0;" ::: "memory");
                __syncthreads();
                if (c + 1 < NCHUNK) {
                    cp_chunk(Wt, sh_w, c + 1, (c + 1) & 1, tid);
                    asm volatile("cp.async.commit_group;" ::: "memory");
                }
                const float* wb = sh_w + (size_t)(c & 1) * KC * DH;
                const int k0 = c * KC;
#pragma unroll
                for (int kk = 0; kk < KC; kk += 2) {
                    float2 a2v[8];
#pragma unroll
                    for (int i = 0; i < 8; i++)
                        a2v[i] = *(const float2*)(hrow[i] + k0 + kk);
#pragma unroll
                    for (int q = 0; q < 2; q++) {
                        const float* wrow = wb + (kk + q) * DH;
                        ull w0 = *(const ull*)(wrow + ncol0);
                        ull w1 = *(const ull*)(wrow + ncol0 + 256);
#pragma unroll
                        for (int i = 0; i < 8; i++) {
                            float av = q ? a2v[i].y : a2v[i].x;
                            ull a2 = pk2(av, av);
                            acc2[i][0] = fma2(a2, w0, acc2[i][0]);
                            acc2[i][1] = fma2(a2, w1, acc2[i][1]);
                        }
                    }
                }
            }
            __syncthreads();  // all matmul reads of sh_hh complete

            // elementwise update of hh
#pragma unroll
            for (int i = 0; i < 8; i++) {
                const size_t rb = (size_t)(tm + 4 * i) * DH;
#pragma unroll
                for (int j = 0; j < 2; j++) {
                    int n0 = ncol0 + 256 * j;
                    float ax, ay;
                    upk2(acc2[i][j], ax, ay);
                    float2 xe = *(const float2*)(sh_xeb + rb + n0);
                    float2 hv = *(const float2*)(sh_h + rb + n0);
                    float2 old = *(const float2*)(sh_hh + rb + n0);
                    float2 nv;
                    nv.x = 0.5f * old.x + 0.5f * fast_tanh(ax + hv.x + xe.x);
                    nv.y = 0.5f * old.y + 0.5f * fast_tanh(ay + hv.y + xe.y);
                    *(float2*)(sh_hh + rb + n0) = nv;
                }
            }
            __syncthreads();  // hh visible for next matmul
        }

        // ---- outer update: h = 0.5 h + 0.5 hh ----
#pragma unroll
        for (int i = 0; i < 8; i++) {
            const size_t rb = (size_t)(tm + 4 * i) * DH;
#pragma unroll
            for (int j = 0; j < 2; j++) {
                int n0 = ncol0 + 256 * j;
                float2 hh = *(const float2*)(sh_hh + rb + n0);
                float2 hv = *(const float2*)(sh_h + rb + n0);
                hv.x = 0.5f * hv.x + 0.5f * hh.x;
                hv.y = 0.5f * hv.y + 0.5f * hh.y;
                *(float2*)(sh_h + rb + n0) = hv;
            }
        }
        __syncthreads();
    }

    // store final h
#pragma unroll
    for (int i = 0; i < 8; i++) {
        int m = row0 + tm + 4 * i;
        const size_t rb = (size_t)(tm + 4 * i) * DH;
#pragma unroll
        for (int j = 0; j < 2; j++) {
            int n0 = ncol0 + 256 * j;
            float2 hv = *(const float2*)(sh_h + rb + n0);
            *(float2*)&g_h[(size_t)m * DH + n0] = hv;
        }
    }
}

// ---------------- launch ----------------
extern "C" void kernel_launch(void* const* d_in, const int* in_sizes, int n_in, void* d_out,
                              int out_size) {
    const float* x = (const float*)d_in[0];
    const float* We = (const float*)d_in[1];
    const float* be = (const float*)d_in[2];
    const float* W = (const float*)d_in[3];
    const float* bW = (const float*)d_in[4];
    const float* u = (const float*)d_in[5];
    const float* Wh = (const float*)d_in[6];
    const float* bh = (const float*)d_in[7];
    const int* steps = (const int*)d_in[8];
    float* out = (float*)d_out;

    float *p_Wet, *p_Wht, *p_xemb, *p_h;
    cudaGetSymbolAddress((void**)&p_Wet, g_Wet);
    cudaGetSymbolAddress((void**)&p_Wht, g_Wht);
    cudaGetSymbolAddress((void**)&p_xemb, g_xemb);
    cudaGetSymbolAddress((void**)&p_h, g_h);

    cudaFuncSetAttribute(k_recurrent, cudaFuncAttributeMaxDynamicSharedMemorySize,
                         REC_SMEM_BYTES);

    k_sigma<<<1, 512>>>(W, u);
    k_prep<<<512, 256>>>(W, We, Wh);

    dim3 g1(DH / 64, NB / 64);
    k_gemm<<<g1, 256>>>(x, p_Wet, be, p_xemb, NB, DH, DIN);

    k_recurrent<<<NB / MT, NT, REC_SMEM_BYTES>>>(bW, steps);

    dim3 g2(DOUT / 64, NB / 64);
    k_gemm<<<g2, 256>>>(p_h, p_Wht, bh, out, NB, DOUT, DH);
}

// round 6
// speedup vs baseline: 1.0024x; 1.0011x over previous
#include <cuda_runtime.h>
#include <cstdint>

#define DIN  1024
#define DH   512
#define NB   8192
#define DOUT 512

#define MT 32            // rows per tile in recurrent kernel
#define NT 512           // threads per CTA (16 warps -> 4 per SMSP)
#define KC 8             // k-chunk staged in smem
#define NCHUNK (DH / KC) // 64
// smem: hh + xeb + h (each MT*DH f32) + W double buffer (2*KC*DH f32)
#define REC_SMEM_BYTES ((3 * MT * DH + 2 * KC * DH) * 4)  // 229376

typedef unsigned long long ull;

// ---------------- scratch (static device allocations: allowed) ----------------
__device__ float g_sigma;
__device__ __align__(16) float g_Wt[DH * DH];     // Wt[k][n] = W[n][k]/sigma
__device__ __align__(16) float g_Wet[DIN * DH];   // Wet[d][j] = We[j][d]
__device__ __align__(16) float g_Wht[DH * DOUT];  // Wht[k][o] = Wh[o][k]
__device__ __align__(16) float g_xemb[NB * DH];
__device__ __align__(16) float g_h[NB * DH];

// ---------------- helpers ----------------
__device__ __forceinline__ ull pk2(float x, float y) {
    ull r;
    asm("mov.b64 %0, {%1,%2};" : "=l"(r) : "f"(x), "f"(y));
    return r;
}
__device__ __forceinline__ void upk2(ull a, float& x, float& y) {
    asm("mov.b64 {%0,%1}, %2;" : "=f"(x), "=f"(y) : "l"(a));
}
// packed fp32x2 FMA (Blackwell): 2x FFMA throughput
__device__ __forceinline__ ull fma2(ull a, ull b, ull c) {
    ull d;
    asm("fma.rn.f32x2 %0, %1, %2, %3;" : "=l"(d) : "l"(a), "l"(b), "l"(c));
    return d;
}
// accurate-enough tanh (~1e-6), immune to -use_fast_math lowering of tanhf
__device__ __forceinline__ float fast_tanh(float x) {
    float a = fabsf(x);
    float e = exp2f(-2.8853900817779268f * a);  // exp(-2a)
    float r = __fdividef(1.0f - e, 1.0f + e);
    return copysignf(r, x);
}

// ---------------- kernel 1: sigma = power-iteration spectral norm ----------------
__global__ void k_sigma(const float* __restrict__ W, const float* __restrict__ u) {
    __shared__ float sv[DH];
    __shared__ float red[DH];
    int t = threadIdx.x;  // 512 threads

    float acc = 0.f;
    for (int i = 0; i < DH; i++) acc += W[(size_t)i * DH + t] * u[i];
    sv[t] = acc;
    red[t] = acc * acc;
    __syncthreads();
    for (int s = 256; s > 0; s >>= 1) {
        if (t < s) red[t] += red[t + s];
        __syncthreads();
    }
    float inv1 = 1.f / (sqrtf(red[0]) + 1e-12f);
    __syncthreads();
    sv[t] *= inv1;  // v
    __syncthreads();
    float sacc = 0.f;
    const float* wr = W + (size_t)t * DH;
    for (int j = 0; j < DH; j++) sacc += wr[j] * sv[j];
    red[t] = sacc * sacc;
    __syncthreads();
    for (int s = 256; s > 0; s >>= 1) {
        if (t < s) red[t] += red[t + s];
        __syncthreads();
    }
    if (t == 0) {
        float ss = red[0];
        g_sigma = ss / (sqrtf(ss) + 1e-12f);
    }
}

// ---------------- kernel 2: scaled/transposed weight prep ----------------
__global__ void k_prep(const float* __restrict__ W, const float* __restrict__ We,
                       const float* __restrict__ Wh) {
    float inv = 1.0f / g_sigma;
    int stride = gridDim.x * blockDim.x;
    int t0 = blockIdx.x * blockDim.x + threadIdx.x;
    for (int idx = t0; idx < DH * DH; idx += stride) {
        int k = idx >> 9, n = idx & 511;
        g_Wt[idx] = W[(size_t)n * DH + k] * inv;
    }
    for (int idx = t0; idx < DIN * DH; idx += stride) {
        int d = idx >> 9, j = idx & 511;
        g_Wet[idx] = We[(size_t)j * DIN + d];
    }
    for (int idx = t0; idx < DH * DOUT; idx += stride) {
        int k = idx / DOUT, o = idx - k * DOUT;
        g_Wht[idx] = Wh[(size_t)o * DH + k];
    }
}

// ---------------- generic tiled GEMM: C[M,N] = A[M,K] @ Bt[K,N] + bias ----------------
__global__ __launch_bounds__(256) void k_gemm(const float* __restrict__ A,
                                              const float* __restrict__ Bt,
                                              const float* __restrict__ bias,
                                              float* __restrict__ C, int M, int N, int K) {
    __shared__ float As[16][64];  // As[k][m]
    __shared__ float Bs[16][64];  // Bs[k][n]
    int tid = threadIdx.x;
    int bx = blockIdx.x;  // N tile
    int by = blockIdx.y;  // M tile
    int tx = tid & 15, ty = tid >> 4;
    float accv[4][4];
#pragma unroll
    for (int i = 0; i < 4; i++)
#pragma unroll
        for (int j = 0; j < 4; j++) accv[i][j] = 0.f;

    for (int k0 = 0; k0 < K; k0 += 16) {
        {
            int r = tid >> 2;
            int c = (tid & 3) * 4;
            float4 av = *(const float4*)&A[(size_t)(by * 64 + r) * K + k0 + c];
            As[c + 0][r] = av.x;
            As[c + 1][r] = av.y;
            As[c + 2][r] = av.z;
            As[c + 3][r] = av.w;
        }
        {
            int kr = tid >> 4;
            int c = (tid & 15) * 4;
            float4 bv = *(const float4*)&Bt[(size_t)(k0 + kr) * N + bx * 64 + c];
            *(float4*)&Bs[kr][c] = bv;
        }
        __syncthreads();
#pragma unroll
        for (int k = 0; k < 16; k++) {
            float a[4], b[4];
#pragma unroll
            for (int i = 0; i < 4; i++) a[i] = As[k][ty * 4 + i];
#pragma unroll
            for (int j = 0; j < 4; j++) b[j] = Bs[k][tx * 4 + j];
#pragma unroll
            for (int i = 0; i < 4; i++)
#pragma unroll
                for (int j = 0; j < 4; j++) accv[i][j] += a[i] * b[j];
        }
        __syncthreads();
    }
#pragma unroll
    for (int i = 0; i < 4; i++) {
        int m = by * 64 + ty * 4 + i;
#pragma unroll
        for (int j = 0; j < 4; j++) {
            int n = bx * 64 + tx * 4 + j;
            C[(size_t)m * N + n] = accv[i][j] + bias[n];
        }
    }
}

// ---------------- kernel 3: fused recurrent core ----------------
__device__ __forceinline__ void cp_chunk(const float* __restrict__ Wt, float* sh_w, int c,
                                         int buf, int tid) {
    const float4* src = (const float4*)(Wt + (size_t)c * KC * DH);
    unsigned sbase = (unsigned)__cvta_generic_to_shared(sh_w + (size_t)buf * KC * DH);
#pragma unroll
    for (int r = 0; r < 2; r++) {
        int e = tid + r * NT;  // float4 index within 8x512 chunk (1024 total)
        asm volatile("cp.async.cg.shared.global [%0], [%1], 16;" ::"r"(sbase + e * 16),
                     "l"(src + e));
    }
}

__global__ __launch_bounds__(NT, 1) void k_recurrent(const float* __restrict__ bW,
                                                     const int* __restrict__ steps_p) {
    extern __shared__ float smem[];
    float* sh_hh = smem;                 // MT*DH : inner state (matmul A operand)
    float* sh_xeb = smem + MT * DH;      // MT*DH : x_emb + bW
    float* sh_h = smem + 2 * MT * DH;    // MT*DH : outer state h
    float* sh_w = smem + 3 * MT * DH;    // 2*KC*DH double buffer

    const int tid = threadIdx.x;
    const int tm = tid >> 7;   // 0..3 (row group)
    const int tn = tid & 127;  // 0..127
    const int ncol0 = 2 * tn;  // + 256*j, j in {0,1}
    const int row0 = blockIdx.x * MT;
    const float* __restrict__ Wt = g_Wt;

    // load x_emb + bW tile, zero h
    for (int idx = tid; idx < MT * DH; idx += NT) {
        int n = idx & (DH - 1);
        sh_xeb[idx] = g_xemb[(size_t)row0 * DH + idx] + bW[n];
        sh_h[idx] = 0.f;
    }

    const float* hrow[8];
#pragma unroll
    for (int i = 0; i < 8; i++) hrow[i] = sh_hh + (size_t)(tm + 4 * i) * DH;

    const int steps = steps_p[0];
    __syncthreads();

    for (int s = 0; s < steps; s++) {
        // ---- inner iter 0 (hh starts at 0 => matmul term is 0) ----
#pragma unroll
        for (int i = 0; i < 8; i++) {
            const size_t rb = (size_t)(tm + 4 * i) * DH;
#pragma unroll
            for (int j = 0; j < 2; j++) {
                int n0 = ncol0 + 256 * j;
                float2 xe = *(const float2*)(sh_xeb + rb + n0);
                float2 hv = *(const float2*)(sh_h + rb + n0);
                float2 o;
                o.x = 0.5f * fast_tanh(hv.x + xe.x);
                o.y = 0.5f * fast_tanh(hv.y + xe.y);
                *(float2*)(sh_hh + rb + n0) = o;
            }
        }
        __syncthreads();

        // ---- inner iters 1..4 : hh = 0.5 hh + 0.5 tanh(hh@Wt + h + xeb) ----
        for (int it = 1; it < 5; it++) {
            ull acc2[8][2];
#pragma unroll
            for (int i = 0; i < 8; i++) {
                acc2[i][0] = 0ull;
                acc2[i][1] = 0ull;
            }

            cp_chunk(Wt, sh_w, 0, 0, tid);
            asm volatile("cp.async.commit_group;" ::: "memory");

            for (int c = 0; c < NCHUNK; c++) {
                asm volatile("cp.async.wait_group 0;" ::: "memory");
                __syncthreads();
                if (c + 1 < NCHUNK) {
                    cp_chunk(Wt, sh_w, c + 1, (c + 1) & 1, tid);
                    asm volatile("cp.async.commit_group;" ::: "memory");
                }
                const float* wb = sh_w + (size_t)(c & 1) * KC * DH;
                const int k0 = c * KC;
#pragma unroll
                for (int kk = 0; kk < KC; kk += 2) {
                    float2 a2v[8];
#pragma unroll
                    for (int i = 0; i < 8; i++)
                        a2v[i] = *(const float2*)(hrow[i] + k0 + kk);
#pragma unroll
                    for (int q = 0; q < 2; q++) {
                        const float* wrow = wb + (kk + q) * DH;
                        ull w0 = *(const ull*)(wrow + ncol0);
                        ull w1 = *(const ull*)(wrow + ncol0 + 256);
#pragma unroll
                        for (int i = 0; i < 8; i++) {
                            float av = q ? a2v[i].y : a2v[i].x;
                            ull a2 = pk2(av, av);
                            acc2[i][0] = fma2(a2, w0, acc2[i][0]);
                            acc2[i][1] = fma2(a2, w1, acc2[i][1]);
                        }
                    }
                }
            }
            __syncthreads();  // all matmul reads of sh_hh complete

            // elementwise update of hh
#pragma unroll
            for (int i = 0; i < 8; i++) {
                const size_t rb = (size_t)(tm + 4 * i) * DH;
#pragma unroll
                for (int j = 0; j < 2; j++) {
                    int n0 = ncol0 + 256 * j;
                    float ax, ay;
                    upk2(acc2[i][j], ax, ay);
                    float2 xe = *(const float2*)(sh_xeb + rb + n0);
                    float2 hv = *(const float2*)(sh_h + rb + n0);
                    float2 old = *(const float2*)(sh_hh + rb + n0);
                    float2 nv;
                    nv.x = 0.5f * old.x + 0.5f * fast_tanh(ax + hv.x + xe.x);
                    nv.y = 0.5f * old.y + 0.5f * fast_tanh(ay + hv.y + xe.y);
                    *(float2*)(sh_hh + rb + n0) = nv;
                }
            }
            __syncthreads();  // hh visible for next matmul
        }

        // ---- outer update: h = 0.5 h + 0.5 hh ----
#pragma unroll
        for (int i = 0; i < 8; i++) {
            const size_t rb = (size_t)(tm + 4 * i) * DH;
#pragma unroll
            for (int j = 0; j < 2; j++) {
                int n0 = ncol0 + 256 * j;
                float2 hh = *(const float2*)(sh_hh + rb + n0);
                float2 hv = *(const float2*)(sh_h + rb + n0);
                hv.x = 0.5f * hv.x + 0.5f * hh.x;
                hv.y = 0.5f * hv.y + 0.5f * hh.y;
                *(float2*)(sh_h + rb + n0) = hv;
            }
        }
        __syncthreads();
    }

    // store final h
#pragma unroll
    for (int i = 0; i < 8; i++) {
        int m = row0 + tm + 4 * i;
        const size_t rb = (size_t)(tm + 4 * i) * DH;
#pragma unroll
        for (int j = 0; j < 2; j++) {
            int n0 = ncol0 + 256 * j;
            float2 hv = *(const float2*)(sh_h + rb + n0);
            *(float2*)&g_h[(size_t)m * DH + n0] = hv;
        }
    }
}

// ---------------- launch ----------------
extern "C" void kernel_launch(void* const* d_in, const int* in_sizes, int n_in, void* d_out,
                              int out_size) {
    const float* x = (const float*)d_in[0];
    const float* We = (const float*)d_in[1];
    const float* be = (const float*)d_in[2];
    const float* W = (const float*)d_in[3];
    const float* bW = (const float*)d_in[4];
    const float* u = (const float*)d_in[5];
    const float* Wh = (const float*)d_in[6];
    const float* bh = (const float*)d_in[7];
    const int* steps = (const int*)d_in[8];
    float* out = (float*)d_out;

    float *p_Wet, *p_Wht, *p_xemb, *p_h;
    cudaGetSymbolAddress((void**)&p_Wet, g_Wet);
    cudaGetSymbolAddress((void**)&p_Wht, g_Wht);
    cudaGetSymbolAddress((void**)&p_xemb, g_xemb);
    cudaGetSymbolAddress((void**)&p_h, g_h);

    cudaFuncSetAttribute(k_recurrent, cudaFuncAttributeMaxDynamicSharedMemorySize,
                         REC_SMEM_BYTES);

    k_sigma<<<1, 512>>>(W, u);
    k_prep<<<512, 256>>>(W, We, Wh);

    dim3 g1(DH / 64, NB / 64);
    k_gemm<<<g1, 256>>>(x, p_Wet, be, p_xemb, NB, DH, DIN);

    k_recurrent<<<NB / MT, NT, REC_SMEM_BYTES>>>(bW, steps);

    dim3 g2(DOUT / 64, NB / 64);
    k_gemm<<<g2, 256>>>(p_h, p_Wht, bh, out, NB, DOUT, DH);
}